// round 3
// baseline (speedup 1.0000x reference)
#include <cuda_runtime.h>

namespace {
constexpr int Hn = 256;    // heads
constexpr int NH = 64;     // complex modes per head
constexpr int Lk = 2048;   // kernel length
constexpr int LH = Lk / 2 + 1;  // 1025 rfft bins
constexpr int NT = 256;    // threads per block
constexpr float TWO_PI = 6.28318530717958647692f;
}

// Inter-kernel scratch: spectrum k_f, 256 heads x 1025 bins (2.1 MB, L2-resident)
__device__ float2 g_kf[Hn * LH];

// ---------------------------------------------------------------------------
// Per-bin rational evaluation + Woodbury correction. dt is pre-folded into
// the numerator constants, so no epilogue scaling is needed.
// ---------------------------------------------------------------------------
__device__ __forceinline__ void compute_bin(
    int j, const float2* __restrict__ shw,
    const float4* __restrict__ sv0, const float4* __restrict__ sv1,
    float2* __restrict__ kf_out)
{
    // ACCURATE sincosf: at j=1024 the angle is ~-pi and |sin| ~ 1.4e-7;
    // __sincosf abs error (~2^-21) can hit exact 0 -> inf -> NaN.
    float sw, cw;
    sincosf(-TWO_PI / (float)Lk * (float)j, &sw, &cw);
    const float dr = 1.0f + cw, di = sw;                   // 1 + omega
    const float dn = __fdividef(1.0f, dr * dr + di * di);
    const float nr = 2.0f * (1.0f - cw), ni = -2.0f * sw;  // 2(1-omega)
    const float zr = (nr * dr + ni * di) * dn;             // z = 2(1-w)/(1+w)
    const float zi = (ni * dr - nr * di) * dn;

    float a00r = 0.f, a00i = 0.f, a01r = 0.f, a01i = 0.f;
    float a10r = 0.f, a10i = 0.f, a11r = 0.f, a11i = 0.f;

#pragma unroll 8
    for (int n = 0; n < NH; n++) {
        const float2 w = shw[n];
        const float er  = zr - w.x;
        const float ei1 = zi - w.y;              // z - w*dt
        const float ei2 = zi + w.y;              // z - conj(w*dt)
        const float er2 = er * er;
        const float rc1 = __fdividef(1.0f, fmaf(ei1, ei1, er2));
        const float rc2 = __fdividef(1.0f, fmaf(ei2, ei2, er2));
        const float t1 = ei1 * rc1, t2 = ei2 * rc2;
        const float rs = rc1 + rc2, rd = rc1 - rc2;
        const float sA  = er * rs;     // Re(1/(z-w)) + Re(1/(z-wbar))
        const float sD  = er * rd;     // Re diff
        const float sB  = t2 - t1;     // Im(1/(z-w)) - Im(1/(z-wbar))
        const float sCn = t1 + t2;     // -(Im sum)
        const float4 v0 = sv0[n];
        const float4 v1 = sv1[n];
        // acc_r += vr*sA - vi*sB ; acc_i += vi*sD - vr*sCn
        a00r = fmaf(v0.x, sA, fmaf(-v0.y, sB,  a00r));
        a00i = fmaf(v0.y, sD, fmaf(-v0.x, sCn, a00i));
        a01r = fmaf(v0.z, sA, fmaf(-v0.w, sB,  a01r));
        a01i = fmaf(v0.w, sD, fmaf(-v0.z, sCn, a01i));
        a10r = fmaf(v1.x, sA, fmaf(-v1.y, sB,  a10r));
        a10i = fmaf(v1.y, sD, fmaf(-v1.x, sCn, a10i));
        a11r = fmaf(v1.z, sA, a11r);            // v11 = |P|^2 : imag == 0
        a11i = fmaf(-v1.z, sCn, a11i);
    }

    // k_f = (r00 - r01*r10/(1+r11)) * 2/(1+omega)
    const float qr = 1.0f + a11r, qi = a11i;
    const float qn = __fdividef(1.0f, qr * qr + qi * qi);
    const float tr = a01r * a10r - a01i * a10i;
    const float ti = a01r * a10i + a01i * a10r;
    const float kr = a00r - (tr * qr + ti * qi) * qn;
    const float ki = a00i - (ti * qr - tr * qi) * qn;
    const float fr =  2.0f * dr * dn;
    const float fi = -2.0f * di * dn;
    *kf_out = make_float2(kr * fr - ki * fi, kr * fi + ki * fr);
}

// ---------------------------------------------------------------------------
// K1: spectrum. grid (4, 256): block x covers 256 bins of head y.
// Nyquist bin (j=1024) piggy-backs on thread 0 of block x==3.
// ---------------------------------------------------------------------------
__global__ void __launch_bounds__(NT) k_spectrum(
    const float* __restrict__ w_ri,
    const float* __restrict__ P_ri,
    const float* __restrict__ B_ri,
    const float* __restrict__ C_ri,
    const float* __restrict__ log_dt)
{
    __shared__ float2 sh_w[NH];
    __shared__ float4 sh_v0[NH];
    __shared__ float4 sh_v1[NH];

    const int h = blockIdx.y;
    const int tid = threadIdx.x;
    const float dt = expf(log_dt[h]);

    if (tid < NH) {
        const int base = (h * NH + tid) * 2;
        const float wr = w_ri[base] * dt, wi = w_ri[base + 1] * dt;
        const float pr = P_ri[base], pi = P_ri[base + 1];
        const float br = B_ri[base], bi = B_ri[base + 1];
        const float cr = C_ri[base], ci = C_ri[base + 1];
        sh_w[tid] = make_float2(wr, wi);
        // dt folded into numerators: v00=B*C, v01=B*conj(P), v10=P*C, v11=|P|^2
        sh_v0[tid] = make_float4(dt * (br * cr - bi * ci), dt * (br * ci + bi * cr),
                                 dt * (br * pr + bi * pi), dt * (bi * pr - br * pi));
        sh_v1[tid] = make_float4(dt * (pr * cr - pi * ci), dt * (pr * ci + pi * cr),
                                 dt * (pr * pr + pi * pi), 0.0f);
    }
    __syncthreads();

    float2* kf = g_kf + h * LH;
    const int j = blockIdx.x * NT + tid;
    compute_bin(j, sh_w, sh_v0, sh_v1, kf + j);
    if (blockIdx.x == 3 && tid == 0)
        compute_bin(1024, sh_w, sh_v0, sh_v1, kf + 1024);
}

// ---------------------------------------------------------------------------
// K2: per-head 2048-pt inverse complex DFT (Stockham), stage 0 fused with
// the Hermitian-mirrored load from global.  Y[t] = sum_j X[j] e^{+2pi i j t/N}
// ---------------------------------------------------------------------------
__global__ void __launch_bounds__(NT) k_ifft(float* __restrict__ out)
{
    __shared__ float2 bufA[Lk];   // 16 KB
    __shared__ float2 bufB[Lk];   // 16 KB

    const int h = blockIdx.x;
    const int tid = threadIdx.x;
    const float2* __restrict__ kf = g_kf + h * LH;

    // stage 0 (sshift=0): a = X[u], b = X[u+1024] via Hermitian mirror.
    for (int u = tid; u < Lk / 2; u += NT) {
        const float2 a = kf[u];
        float2 b;
        if (u == 0) {
            b = kf[1024];
        } else {
            const float2 t = kf[1024 - u];
            b = make_float2(t.x, -t.y);
        }
        float s, c;
        __sincosf(TWO_PI / (float)Lk * (float)u, &s, &c);
        const float ax = a.x - b.x, ay = a.y - b.y;
        // outputs 2u, 2u+1 are 16B-contiguous: single float4 store
        reinterpret_cast<float4*>(bufA)[u] =
            make_float4(a.x + b.x, a.y + b.y,
                        ax * c - ay * s, ax * s + ay * c);
    }
    __syncthreads();

    float2* cur = bufA;
    float2* nxt = bufB;
#pragma unroll 1
    for (int s = 1; s < 11; s++) {
        const float step = TWO_PI * (float)(1 << s) / (float)Lk;
#pragma unroll 4
        for (int u = tid; u < Lk / 2; u += NT) {
            const int p  = u >> s;
            const int lo = u & ((1 << s) - 1);
            float sv, cv;
            __sincosf(step * (float)p, &sv, &cv);   // args inside (-pi,pi): safe
            const float2 a = cur[u];
            const float2 b = cur[u + Lk / 2];
            const int o = (p << (s + 1)) | lo;
            nxt[o] = make_float2(a.x + b.x, a.y + b.y);
            const float ax = a.x - b.x, ay = a.y - b.y;
            nxt[o + (1 << s)] =
                make_float2(ax * cv - ay * sv, ax * sv + ay * cv);
        }
        __syncthreads();
        float2* t = cur; cur = nxt; nxt = t;
    }
    // 10 swaps -> cur == bufA holds the final result

    const float inv = 1.0f / (float)Lk;
    float* o = out + h * Lk;
#pragma unroll 8
    for (int t = tid; t < Lk; t += NT)
        o[t] = cur[t].x * inv;
}

extern "C" void kernel_launch(void* const* d_in, const int* in_sizes, int n_in,
                              void* d_out, int out_size) {
    // metadata order: w_ri, P_ri, B_ri, C_ri, log_dt, L (L fixed at 2048)
    k_spectrum<<<dim3(4, Hn), NT>>>(
        (const float*)d_in[0],
        (const float*)d_in[1],
        (const float*)d_in[2],
        (const float*)d_in[3],
        (const float*)d_in[4]);
    k_ifft<<<Hn, NT>>>((float*)d_out);
}